// round 5
// baseline (speedup 1.0000x reference)
#include <cuda_runtime.h>
#include <cstdint>

// sampling_map: [B=64, C=3, H=512, W=512] fp32 row-major.
// GRID=4 -> 128x128 cells; channel-sum; valid 3x3 window over 4x4 grid -> 2x2;
// argmax (TOP_K=1) -> coords (idx//2, idx%2), output shape [B,1,2].
// Output written as FLOAT32 (hypothesis: harness compares float32).
// Mean factor 1/16384 is uniform -> argmax-invariant -> dropped.
static constexpr int B = 64;
static constexpr int C = 3;
static constexpr int H = 512;
static constexpr int W = 512;
static constexpr int W4 = W / 4;       // 128 float4 per image row
static constexpr int THREADS = 1024;   // 32 warps

__global__ __launch_bounds__(THREADS) void region_selector_kernel(
    const float* __restrict__ in, float* __restrict__ out) {
    const int b    = blockIdx.x;
    const int t    = threadIdx.x;
    const int w    = t >> 5;
    const int lane = t & 31;

    float acc[4][4];
#pragma unroll
    for (int i = 0; i < 4; i++)
#pragma unroll
        for (int j = 0; j < 4; j++) acc[i][j] = 0.0f;

    const float4* __restrict__ base =
        reinterpret_cast<const float4*>(in) + (size_t)b * (C * H * W4);

#pragma unroll
    for (int c = 0; c < C; c++) {
        const float4* __restrict__ chan = base + (size_t)c * (H * W4);
#pragma unroll
        for (int gy = 0; gy < 4; gy++) {
#pragma unroll
            for (int k = 0; k < 4; k++) {
                const int row = gy * 128 + k * 32 + w;   // 32 warps cover 32 rows
                const float4* __restrict__ rowp = chan + (size_t)row * W4;
#pragma unroll
                for (int gx = 0; gx < 4; gx++) {
                    float4 v = __ldg(&rowp[gx * 32 + lane]);  // 512B coalesced/warp
                    acc[gy][gx] += (v.x + v.y) + (v.z + v.w);
                }
            }
        }
    }

    // Warp-reduce the 16 accumulators, then combine 32 warps via smem.
#pragma unroll
    for (int i = 0; i < 4; i++)
#pragma unroll
        for (int j = 0; j < 4; j++)
#pragma unroll
            for (int off = 16; off > 0; off >>= 1)
                acc[i][j] += __shfl_down_sync(0xFFFFFFFFu, acc[i][j], off);

    __shared__ float s_part[32][16];
    if (lane == 0) {
#pragma unroll
        for (int i = 0; i < 4; i++)
#pragma unroll
            for (int j = 0; j < 4; j++)
                s_part[w][i * 4 + j] = acc[i][j];
    }
    __syncthreads();

    if (t == 0) {
        float cs[16];
#pragma unroll
        for (int k = 0; k < 16; k++) {
            float s = 0.0f;
#pragma unroll
            for (int ww = 0; ww < 32; ww++) s += s_part[ww][k];
            cs[k] = s;
        }

        // Four valid 3x3 window sums over the 4x4 grid.
        float ws[4];
#pragma unroll
        for (int i = 0; i < 2; i++) {
#pragma unroll
            for (int j = 0; j < 2; j++) {
                float s = 0.0f;
#pragma unroll
                for (int di = 0; di < 3; di++)
#pragma unroll
                    for (int dj = 0; dj < 3; dj++)
                        s += cs[(i + di) * 4 + (j + dj)];
                ws[i * 2 + j] = s;
            }
        }

        int best_idx = 0;
        float best = ws[0];
#pragma unroll
        for (int k = 1; k < 4; k++)
            if (ws[k] > best) { best = ws[k]; best_idx = k; }

        float row_out = (float)(best_idx >> 1);
        float col_out = (float)(best_idx & 1);

        // Diagnostic (normal data never triggers): NaN window sums would mean
        // the input dtype interpretation is wrong -> emit (1,1) so the failure
        // signature differs from the all-zeros case.
        if (!(ws[0] == ws[0])) { row_out = 1.0f; col_out = 1.0f; }

        out[b * 2 + 0] = row_out;   // row = idx // 2
        out[b * 2 + 1] = col_out;   // col = idx % 2
    }
}

extern "C" void kernel_launch(void* const* d_in, const int* in_sizes, int n_in,
                              void* d_out, int out_size) {
    (void)in_sizes; (void)n_in; (void)out_size;
    const float* in = (const float*)d_in[0];
    float* out = (float*)d_out;
    region_selector_kernel<<<B, THREADS>>>(in, out);
}

// round 6
// speedup vs baseline: 1.2319x; 1.2319x over previous
#include <cuda_runtime.h>
#include <cstdint>

// sampling_map: [B=64, C=3, H=512, W=512] fp32 row-major.
// GRID=4 -> 128x128 cells; channel-sum; valid 3x3 window over 4x4 grid -> 2x2;
// argmax (TOP_K=1) -> coords (idx//2, idx%2), output [B,1,2] as FLOAT32.
// Mean factor 1/16384 is uniform -> argmax-invariant -> dropped.
static constexpr int B = 64;
static constexpr int C = 3;
static constexpr int H = 512;
static constexpr int W = 512;
static constexpr int GH = 128;
static constexpr int GW = 128;
static constexpr int W4 = W / 4;       // 128 float4 per image row

// Device-global scratch (zero-init, allocation-guard safe).
__device__ float        g_cells[B * 16];
__device__ unsigned int g_count[B];

// One block per (batch, cell): 1024 blocks x 256 threads -> full-chip stream.
__global__ __launch_bounds__(256) void region_selector_kernel(
    const float* __restrict__ in, float* __restrict__ out) {
    const int blk  = blockIdx.x;
    const int cell = blk & 15;
    const int b    = blk >> 4;
    const int gy   = cell >> 2;
    const int gx   = cell & 3;

    const int t     = threadIdx.x;
    const int lane8 = t & 7;    // 8 threads cover one 128-float row (4 float4 ea)
    const int r0    = t >> 3;   // base row 0..31

    float acc = 0.0f;
#pragma unroll
    for (int c = 0; c < C; c++) {
        const float4* __restrict__ base = reinterpret_cast<const float4*>(in) +
            (((size_t)(b * C + c) * H) + (size_t)gy * GH) * W4 + gx * (GW / 4);
#pragma unroll
        for (int m = 0; m < 4; m++) {
            const float4* __restrict__ rowp = base + (size_t)(r0 + m * 32) * W4;
#pragma unroll
            for (int j = 0; j < 4; j++) {
                float4 v = __ldg(&rowp[lane8 + j * 8]);
                acc += (v.x + v.y) + (v.z + v.w);
            }
        }
    }

    // Block reduction: warp shuffles, then 8 warps via smem.
    __shared__ float warp_sums[8];
#pragma unroll
    for (int off = 16; off > 0; off >>= 1)
        acc += __shfl_down_sync(0xFFFFFFFFu, acc, off);
    if ((t & 31) == 0) warp_sums[t >> 5] = acc;
    __syncthreads();

    if (t == 0) {
        float s = 0.0f;
#pragma unroll
        for (int w = 0; w < 8; w++) s += warp_sums[w];
        g_cells[blk] = s;
        __threadfence();                        // publish before the ticket
        const unsigned int done = atomicAdd(&g_count[b], 1u);
        if (done == 15u) {
            // Last finishing block of this batch: finalize.
            float cs[16];
#pragma unroll
            for (int k = 0; k < 16; k++)
                cs[k] = __ldcg(&g_cells[(b << 4) + k]);   // L2 (coherent) reads

            float ws[4];
#pragma unroll
            for (int i = 0; i < 2; i++) {
#pragma unroll
                for (int j = 0; j < 2; j++) {
                    float s2 = 0.0f;
#pragma unroll
                    for (int di = 0; di < 3; di++)
#pragma unroll
                        for (int dj = 0; dj < 3; dj++)
                            s2 += cs[(i + di) * 4 + (j + dj)];
                    ws[i * 2 + j] = s2;
                }
            }
            int best_idx = 0;
            float best = ws[0];
#pragma unroll
            for (int k = 1; k < 4; k++)
                if (ws[k] > best) { best = ws[k]; best_idx = k; }

            out[b * 2 + 0] = (float)(best_idx >> 1);  // row = idx // 2
            out[b * 2 + 1] = (float)(best_idx & 1);   // col = idx % 2
            g_count[b] = 0;                           // reset for graph replay
        }
    }
}

extern "C" void kernel_launch(void* const* d_in, const int* in_sizes, int n_in,
                              void* d_out, int out_size) {
    (void)in_sizes; (void)n_in; (void)out_size;
    const float* in = (const float*)d_in[0];
    float* out = (float*)d_out;
    region_selector_kernel<<<B * 16, 256>>>(in, out);
}

// round 7
// speedup vs baseline: 1.2330x; 1.0009x over previous
#include <cuda_runtime.h>
#include <cstdint>

// sampling_map: [B=64, C=3, H=512, W=512] fp32 row-major.
// GRID=4 -> 128x128 cells; channel-sum; valid 3x3 window over 4x4 grid -> 2x2;
// argmax (TOP_K=1) -> coords (idx//2, idx%2), output [B,1,2] as FLOAT32.
// Mean factor 1/16384 is uniform -> argmax-invariant -> dropped.
static constexpr int B = 64;
static constexpr int C = 3;
static constexpr int H = 512;
static constexpr int W = 512;
static constexpr int W4 = W / 4;            // 128 float4 per image row
static constexpr int ROWS_PER_BLK = 32;     // 32 contiguous rows = 64 KB span
static constexpr int CHUNKS_PER_IMG = H / ROWS_PER_BLK;   // 16
static constexpr int BLOCKS = B * C * CHUNKS_PER_IMG;     // 3072
static constexpr int BLOCKS_PER_BATCH = C * CHUNKS_PER_IMG; // 48
static constexpr int SLOTS = C * 4;         // 12 partials per cell (c, sub)

// Scratch: g_part[b][cell(16)][slot(12)], ticket per batch.
__device__ float        g_part[B * 16 * SLOTS];
__device__ unsigned int g_count[B];

__global__ __launch_bounds__(256) void region_selector_kernel(
    const float* __restrict__ in, float* __restrict__ out) {
    const int blk   = blockIdx.x;
    const int chunk = blk % CHUNKS_PER_IMG;          // 0..15 within (b,c)
    const int c     = (blk / CHUNKS_PER_IMG) % C;
    const int b     = blk / BLOCKS_PER_BATCH;
    const int gy    = chunk >> 2;                    // 128-row band
    const int sub   = chunk & 3;                     // 32-row sub-chunk

    const int t     = threadIdx.x;
    const int w     = t >> 5;
    const int lane  = t & 31;
    const int r     = t >> 3;     // 0..31: row within chunk
    const int lane8 = t & 7;      // 8 threads per row

    // Fully contiguous 64KB block span: rows [gy*128 + sub*32, +32) of (b,c).
    const float4* __restrict__ rowp = reinterpret_cast<const float4*>(in) +
        ((size_t)(b * C + c) * H + (size_t)(gy * 128 + sub * 32 + r)) * W4;

    // Each thread covers its full row (16 float4), split into 4 gx accumulators.
    float acc[4];
#pragma unroll
    for (int g = 0; g < 4; g++) acc[g] = 0.0f;
#pragma unroll
    for (int g = 0; g < 4; g++) {
#pragma unroll
        for (int j = 0; j < 4; j++) {
            float4 v = __ldcs(&rowp[g * 32 + lane8 + j * 8]);  // streaming, evict-first
            acc[g] += (v.x + v.y) + (v.z + v.w);
        }
    }

    // Warp-reduce the 4 accumulators; combine 8 warps in smem.
#pragma unroll
    for (int g = 0; g < 4; g++)
#pragma unroll
        for (int off = 16; off > 0; off >>= 1)
            acc[g] += __shfl_down_sync(0xFFFFFFFFu, acc[g], off);

    __shared__ float s_part[8][4];
    __shared__ float cs[16];
    __shared__ int   s_last;
    if (lane == 0) {
#pragma unroll
        for (int g = 0; g < 4; g++) s_part[w][g] = acc[g];
    }
    __syncthreads();

    if (t < 4) {
        float s = 0.0f;
#pragma unroll
        for (int ww = 0; ww < 8; ww++) s += s_part[ww][t];
        // slot layout: [cell][c*4 + sub]
        g_part[((b * 16) + (gy * 4 + t)) * SLOTS + c * 4 + sub] = s;
        __threadfence();                          // publish own store
    }
    __syncthreads();

    if (t == 0) {
        const unsigned int done = atomicAdd(&g_count[b], 1u);
        s_last = (done == BLOCKS_PER_BATCH - 1) ? 1 : 0;
    }
    __syncthreads();

    if (s_last) {
        // Block-wide cooperative finalize (deterministic fixed-order sums).
        if (t < 16) {
            float s = 0.0f;
            const float* p = &g_part[((b * 16) + t) * SLOTS];
#pragma unroll
            for (int k = 0; k < SLOTS; k++) s += __ldcg(&p[k]);
            cs[t] = s;
        }
        __syncthreads();
        if (t == 0) {
            float ws[4];
#pragma unroll
            for (int i = 0; i < 2; i++) {
#pragma unroll
                for (int j = 0; j < 2; j++) {
                    float s2 = 0.0f;
#pragma unroll
                    for (int di = 0; di < 3; di++)
#pragma unroll
                        for (int dj = 0; dj < 3; dj++)
                            s2 += cs[(i + di) * 4 + (j + dj)];
                    ws[i * 2 + j] = s2;
                }
            }
            int best_idx = 0;
            float best = ws[0];
#pragma unroll
            for (int k = 1; k < 4; k++)
                if (ws[k] > best) { best = ws[k]; best_idx = k; }

            out[b * 2 + 0] = (float)(best_idx >> 1);  // row = idx // 2
            out[b * 2 + 1] = (float)(best_idx & 1);   // col = idx % 2
            g_count[b] = 0;                           // reset for graph replay
        }
    }
}

extern "C" void kernel_launch(void* const* d_in, const int* in_sizes, int n_in,
                              void* d_out, int out_size) {
    (void)in_sizes; (void)n_in; (void)out_size;
    const float* in = (const float*)d_in[0];
    float* out = (float*)d_out;
    region_selector_kernel<<<BLOCKS, 256>>>(in, out);
}